// round 1
// baseline (speedup 1.0000x reference)
#include <cuda_runtime.h>

#define NX     768
#define NHEAD  12
#define SEQ    2048
#define HD     64
#define BS     2
#define QKV3   (3 * NX)

// Scratch (no cudaMalloc allowed): 37.7 MB + 12.6 MB
__device__ float g_qkv[(size_t)BS * SEQ * QKV3];
__device__ float g_attn[(size_t)BS * SEQ * NX];

// ---------------------------------------------------------------------------
// C[M,N] = A[M,K] @ B[K,N] + bias[N]   (row-major, M%BM==0, N%BN==0, K%BK==0)
// ---------------------------------------------------------------------------
template <int BM, int BN, int BK>
__global__ __launch_bounds__(256) void gemm_bias_kernel(
    const float* __restrict__ A, const float* __restrict__ B,
    const float* __restrict__ bias, float* __restrict__ C,
    int M, int N, int K)
{
    __shared__ float As[BM][BK];
    __shared__ float Bs[BK][BN];

    const int tid = threadIdx.x;            // 256 threads
    const int tx = tid & 15;                // 16 x 16 thread grid
    const int ty = tid >> 4;
    const int row0 = blockIdx.y * BM;
    const int col0 = blockIdx.x * BN;

    float acc[4][4] = {};

    for (int k0 = 0; k0 < K; k0 += BK) {
        #pragma unroll
        for (int i = tid; i < BM * BK; i += 256) {
            int r = i / BK, c = i % BK;
            As[r][c] = A[(size_t)(row0 + r) * K + k0 + c];
        }
        #pragma unroll
        for (int i = tid; i < BK * BN; i += 256) {
            int r = i / BN, c = i % BN;
            Bs[r][c] = B[(size_t)(k0 + r) * N + col0 + c];
        }
        __syncthreads();

        #pragma unroll
        for (int kk = 0; kk < BK; kk++) {
            float a[4];
            #pragma unroll
            for (int i = 0; i < 4; i++) a[i] = As[ty * 4 + i][kk];
            float4 b4 = *(const float4*)&Bs[kk][tx * 4];
            float b[4] = {b4.x, b4.y, b4.z, b4.w};
            #pragma unroll
            for (int i = 0; i < 4; i++)
                #pragma unroll
                for (int j = 0; j < 4; j++)
                    acc[i][j] += a[i] * b[j];
        }
        __syncthreads();
    }

    float4 bia = *(const float4*)&bias[col0 + tx * 4];
    #pragma unroll
    for (int i = 0; i < 4; i++) {
        int r = row0 + ty * 4 + i;
        float4 o;
        o.x = acc[i][0] + bia.x;
        o.y = acc[i][1] + bia.y;
        o.z = acc[i][2] + bia.z;
        o.w = acc[i][3] + bia.w;
        *(float4*)&C[(size_t)r * N + col0 + tx * 4] = o;
    }
}

// ---------------------------------------------------------------------------
// Flash attention over the "raw reshape" layout.
// q[b,h,s,d] = qkv[b][u/12][(u%12)*64 + d],          u = h*2048 + s
// k: same + 768 channel offset;  v: same + 1536.
// out[b,s,h*64+d]  (standard merge for the output side)
// ---------------------------------------------------------------------------
__global__ __launch_bounds__(128) void attn_kernel(
    const float* __restrict__ qkv, const float* __restrict__ amask,
    float* __restrict__ attn_out)
{
    constexpr int BM = 128, BN = 32;
    const int qb  = blockIdx.x;
    const int h   = blockIdx.y;
    const int b   = blockIdx.z;
    const int tid = threadIdx.x;
    const int qidx = qb * BM + tid;

    __shared__ float Ks[BN][HD];
    __shared__ float Vs[BN][HD];
    __shared__ float Ams[SEQ];

    const float* base = qkv + (size_t)b * SEQ * QKV3;

    for (int i = tid; i < SEQ; i += BM) Ams[i] = amask[b * SEQ + i];

    float q[HD];
    {
        int u = h * SEQ + qidx;
        const float4* qp = (const float4*)(base + (u / 12) * QKV3 + (u % 12) * HD);
        #pragma unroll
        for (int i = 0; i < HD / 4; i++) {
            float4 t = qp[i];
            q[4*i] = t.x; q[4*i+1] = t.y; q[4*i+2] = t.z; q[4*i+3] = t.w;
        }
    }

    float acc[HD];
    #pragma unroll
    for (int d = 0; d < HD; d++) acc[d] = 0.f;
    float m = -3.0e38f, l = 0.f;

    const int nkb = (qb * BM + BM) / BN;   // causal: keys 0 .. qb*128+127
    for (int kb = 0; kb < nkb; kb++) {
        const int k0 = kb * BN;
        __syncthreads();   // protect previous iteration's Ks/Vs reads
        #pragma unroll
        for (int i = tid; i < BN * HD / 4; i += BM) {
            int j = (i * 4) / HD;
            int d = (i * 4) % HD;
            int u = h * SEQ + k0 + j;
            const float* rowbase = base + (u / 12) * QKV3 + (u % 12) * HD + d;
            ((float4*)Ks)[i] = *(const float4*)(rowbase + NX);       // K
            ((float4*)Vs)[i] = *(const float4*)(rowbase + 2 * NX);   // V
        }
        __syncthreads();

        float s[BN];
        #pragma unroll
        for (int j = 0; j < BN; j++) {
            const float4* kp = (const float4*)Ks[j];
            float sum = 0.f;
            #pragma unroll
            for (int i = 0; i < HD / 4; i++) {
                float4 t = kp[i];
                sum += q[4*i] * t.x + q[4*i+1] * t.y
                     + q[4*i+2] * t.z + q[4*i+3] * t.w;
            }
            int k = k0 + j;
            // reference: w*mask + (-10000)*(1-mask), then + attention_mask[b,k]
            s[j] = (k <= qidx) ? (sum * 0.125f + Ams[k]) : (-10000.f + Ams[k]);
        }

        float mb = s[0];
        #pragma unroll
        for (int j = 1; j < BN; j++) mb = fmaxf(mb, s[j]);
        float mn = fmaxf(m, mb);
        float corr = __expf(m - mn);
        l *= corr;
        #pragma unroll
        for (int d = 0; d < HD; d++) acc[d] *= corr;

        #pragma unroll
        for (int j = 0; j < BN; j++) {
            float p = __expf(s[j] - mn);
            l += p;
            const float4* vp = (const float4*)Vs[j];
            #pragma unroll
            for (int i = 0; i < HD / 4; i++) {
                float4 t = vp[i];
                acc[4*i]   += p * t.x;
                acc[4*i+1] += p * t.y;
                acc[4*i+2] += p * t.z;
                acc[4*i+3] += p * t.w;
            }
        }
        m = mn;
    }

    float inv = 1.f / l;
    float4* op = (float4*)(attn_out + ((size_t)b * SEQ + qidx) * NX + h * HD);
    #pragma unroll
    for (int i = 0; i < HD / 4; i++) {
        float4 t;
        t.x = acc[4*i]   * inv;
        t.y = acc[4*i+1] * inv;
        t.z = acc[4*i+2] * inv;
        t.w = acc[4*i+3] * inv;
        op[i] = t;
    }
}

// ---------------------------------------------------------------------------
extern "C" void kernel_launch(void* const* d_in, const int* in_sizes, int n_in,
                              void* d_out, int out_size)
{
    const float* hidden = (const float*)d_in[0];
    const float* amask  = (const float*)d_in[1];
    const float* w_attn = (const float*)d_in[2];
    const float* b_attn = (const float*)d_in[3];
    const float* w_proj = (const float*)d_in[4];
    const float* b_proj = (const float*)d_in[5];
    float* out = (float*)d_out;

    float *qkv, *attn;
    cudaGetSymbolAddress((void**)&qkv,  g_qkv);
    cudaGetSymbolAddress((void**)&attn, g_attn);

    const int M = BS * SEQ;   // 4096

    gemm_bias_kernel<64, 64, 16>
        <<<dim3(QKV3 / 64, M / 64), 256>>>(hidden, w_attn, b_attn, qkv, M, QKV3, NX);

    attn_kernel<<<dim3(SEQ / 128, NHEAD, BS), 128>>>(qkv, amask, attn);

    gemm_bias_kernel<64, 64, 16>
        <<<dim3(NX / 64, M / 64), 256>>>(attn, w_proj, b_proj, out, M, NX, NX);
}

// round 5
// speedup vs baseline: 1.1249x; 1.1249x over previous
#include <cuda_runtime.h>

#define NX     768
#define NHEAD  12
#define SEQ    2048
#define HD     64
#define BS     2
#define QKV3   (3 * NX)

// Scratch (no cudaMalloc allowed)
__device__ float g_qkv[(size_t)BS * SEQ * QKV3];
__device__ float g_attn[(size_t)BS * SEQ * NX];

// ---------------------------------------------------------------------------
// C[M,N] = A[M,K] @ B[K,N] + bias[N]
// BM=128, BN=64, BK=16, 256 threads, 8x4 microtile, As transposed+padded.
// ---------------------------------------------------------------------------
__global__ __launch_bounds__(256) void gemm_bias_kernel(
    const float* __restrict__ A, const float* __restrict__ B,
    const float* __restrict__ bias, float* __restrict__ C,
    int M, int N, int K)
{
    constexpr int BM = 128, BN = 64, BK = 16;
    __shared__ float As[BK][BM + 4];   // transposed, padded
    __shared__ float Bs[BK][BN];

    const int tid = threadIdx.x;
    const int tx = tid & 15;           // 0..15 -> 4 cols each
    const int ty = tid >> 4;           // 0..15 -> 8 rows each
    const int row0 = blockIdx.y * BM;
    const int col0 = blockIdx.x * BN;

    float acc[8][4] = {};

    for (int k0 = 0; k0 < K; k0 += BK) {
        // Load A tile: 128x16 = 512 float4; 256 threads -> 2 each.
        #pragma unroll
        for (int i = tid; i < BM * BK / 4; i += 256) {
            int r  = i >> 2;           // row in tile (BK/4 = 4 vec per row)
            int c4 = i & 3;
            float4 t = *(const float4*)&A[(size_t)(row0 + r) * K + k0 + c4 * 4];
            As[c4 * 4 + 0][r] = t.x;
            As[c4 * 4 + 1][r] = t.y;
            As[c4 * 4 + 2][r] = t.z;
            As[c4 * 4 + 3][r] = t.w;
        }
        // Load B tile: 16x64 = 256 float4; 1 each.
        {
            int r  = tid >> 4;         // BN/4 = 16 vec per row
            int c4 = tid & 15;
            *(float4*)&Bs[r][c4 * 4] =
                *(const float4*)&B[(size_t)(k0 + r) * N + col0 + c4 * 4];
        }
        __syncthreads();

        #pragma unroll
        for (int kk = 0; kk < BK; kk++) {
            float4 a0 = *(const float4*)&As[kk][ty * 8];
            float4 a1 = *(const float4*)&As[kk][ty * 8 + 4];
            float4 b  = *(const float4*)&Bs[kk][tx * 4];
            float a[8] = {a0.x, a0.y, a0.z, a0.w, a1.x, a1.y, a1.z, a1.w};
            float bb[4] = {b.x, b.y, b.z, b.w};
            #pragma unroll
            for (int i = 0; i < 8; i++)
                #pragma unroll
                for (int j = 0; j < 4; j++)
                    acc[i][j] += a[i] * bb[j];
        }
        __syncthreads();
    }

    float4 bia = *(const float4*)&bias[col0 + tx * 4];
    #pragma unroll
    for (int i = 0; i < 8; i++) {
        int r = row0 + ty * 8 + i;
        float4 o;
        o.x = acc[i][0] + bia.x;
        o.y = acc[i][1] + bia.y;
        o.z = acc[i][2] + bia.z;
        o.w = acc[i][3] + bia.w;
        *(float4*)&C[(size_t)r * N + col0 + tx * 4] = o;
    }
}

// ---------------------------------------------------------------------------
// Flash attention over the "raw reshape" layout.
// q[b,h,s,d] = qkv[b][u/12][(u%12)*64 + d],   u = h*2048 + s
// k: +768 channel offset; v: +1536. out[b,s,h*64+d].
// 128 threads = 128 query rows per block; 32-key tiles in smem.
// ---------------------------------------------------------------------------
__global__ __launch_bounds__(128) void attn_kernel(
    const float* __restrict__ qkv, const float* __restrict__ amask,
    float* __restrict__ attn_out)
{
    constexpr int BM = 128, BN = 32;
    const int qb  = blockIdx.x;
    const int h   = blockIdx.y;
    const int b   = blockIdx.z;
    const int tid = threadIdx.x;
    const int qidx = qb * BM + tid;

    __shared__ float Ks[BN][HD];
    __shared__ float Vs[BN][HD];
    __shared__ float Ams[SEQ];

    const float* base = qkv + (size_t)b * SEQ * QKV3;

    for (int i = tid; i < SEQ; i += BM) Ams[i] = amask[b * SEQ + i];

    float q[HD];
    {
        int u = h * SEQ + qidx;
        const float4* qp = (const float4*)(base + (u / 12) * QKV3 + (u % 12) * HD);
        #pragma unroll
        for (int i = 0; i < HD / 4; i++) {
            float4 t = qp[i];
            q[4*i] = t.x; q[4*i+1] = t.y; q[4*i+2] = t.z; q[4*i+3] = t.w;
        }
    }

    float acc[HD];
    #pragma unroll
    for (int d = 0; d < HD; d++) acc[d] = 0.f;
    float m = -3.0e38f, l = 0.f;

    const int nkb = (qb * BM + BM) / BN;   // causal
    for (int kb = 0; kb < nkb; kb++) {
        const int k0 = kb * BN;
        __syncthreads();   // protect previous iteration's Ks/Vs reads
        #pragma unroll
        for (int i = tid; i < BN * HD / 4; i += BM) {
            int j  = i >> 4;           // HD/4 = 16 vec per key row
            int d4 = i & 15;
            int u = h * SEQ + k0 + j;
            const float* rowbase = base + (u / 12) * QKV3 + (u % 12) * HD + d4 * 4;
            ((float4*)Ks)[i] = *(const float4*)(rowbase + NX);       // K
            ((float4*)Vs)[i] = *(const float4*)(rowbase + 2 * NX);   // V
        }
        __syncthreads();

        float s[BN];
        #pragma unroll
        for (int j = 0; j < BN; j++) {
            const float4* kp = (const float4*)Ks[j];
            // 8 independent FMA chains -> ILP to saturate the FFMA pipe
            float4 sa = {0.f, 0.f, 0.f, 0.f};
            float4 sb = {0.f, 0.f, 0.f, 0.f};
            #pragma unroll
            for (int i = 0; i < HD / 4; i += 2) {
                float4 t0 = kp[i];
                float4 t1 = kp[i + 1];
                sa.x += q[4*i+0] * t0.x;
                sa.y += q[4*i+1] * t0.y;
                sa.z += q[4*i+2] * t0.z;
                sa.w += q[4*i+3] * t0.w;
                sb.x += q[4*i+4] * t1.x;
                sb.y += q[4*i+5] * t1.y;
                sb.z += q[4*i+6] * t1.z;
                sb.w += q[4*i+7] * t1.w;
            }
            float sum = (sa.x + sa.y) + (sa.z + sa.w)
                      + (sb.x + sb.y) + (sb.z + sb.w);
            int k = k0 + j;
            s[j] = (k <= qidx) ? (sum * 0.125f + Ams[k]) : (-10000.f + Ams[k]);
        }

        float mb = s[0];
        #pragma unroll
        for (int j = 1; j < BN; j++) mb = fmaxf(mb, s[j]);
        float mn = fmaxf(m, mb);
        float corr = __expf(m - mn);
        l *= corr;
        #pragma unroll
        for (int d = 0; d < HD; d++) acc[d] *= corr;

        #pragma unroll
        for (int j = 0; j < BN; j++) {
            float p = __expf(s[j] - mn);
            l += p;
            const float4* vp = (const float4*)Vs[j];
            #pragma unroll
            for (int i = 0; i < HD / 4; i++) {
                float4 t = vp[i];
                acc[4*i]   += p * t.x;
                acc[4*i+1] += p * t.y;
                acc[4*i+2] += p * t.z;
                acc[4*i+3] += p * t.w;
            }
        }
        m = mn;
    }

    float inv = 1.f / l;
    float4* op = (float4*)(attn_out + ((size_t)b * SEQ + qidx) * NX + h * HD);
    #pragma unroll
    for (int i = 0; i < HD / 4; i++) {
        float4 t;
        t.x = acc[4*i]   * inv;
        t.y = acc[4*i+1] * inv;
        t.z = acc[4*i+2] * inv;
        t.w = acc[4*i+3] * inv;
        op[i] = t;
    }
}

// ---------------------------------------------------------------------------
extern "C" void kernel_launch(void* const* d_in, const int* in_sizes, int n_in,
                              void* d_out, int out_size)
{
    const float* hidden = (const float*)d_in[0];
    const float* amask  = (const float*)d_in[1];
    const float* w_attn = (const float*)d_in[2];
    const float* b_attn = (const float*)d_in[3];
    const float* w_proj = (const float*)d_in[4];
    const float* b_proj = (const float*)d_in[5];
    float* out = (float*)d_out;

    float *qkv, *attn;
    cudaGetSymbolAddress((void**)&qkv,  g_qkv);
    cudaGetSymbolAddress((void**)&attn, g_attn);

    const int M = BS * SEQ;   // 4096

    gemm_bias_kernel<<<dim3(QKV3 / 64, M / 128), 256>>>(hidden, w_attn, b_attn, qkv, M, QKV3, NX);

    attn_kernel<<<dim3(SEQ / 128, NHEAD, BS), 128>>>(qkv, amask, attn);

    gemm_bias_kernel<<<dim3(NX / 64, M / 128), 256>>>(attn, w_proj, b_proj, out, M, NX, NX);
}

// round 8
// speedup vs baseline: 1.2283x; 1.0919x over previous
#include <cuda_runtime.h>

#define NX     768
#define NHEAD  12
#define SEQ    2048
#define HD     64
#define BS     2
#define QKV3   (3 * NX)

typedef unsigned long long ull;

// packed f32x2 helpers (FFMA2 is only reachable via PTX)
#define FMA2(d, a, b, c) \
    asm("fma.rn.f32x2 %0, %1, %2, %3;" : "=l"(d) : "l"(a), "l"(b), "l"(c))
#define MUL2(d, a, b) \
    asm("mul.rn.f32x2 %0, %1, %2;" : "=l"(d) : "l"(a), "l"(b))
#define PACK2(d, lo, hi) \
    asm("mov.b64 %0, {%1, %2};" : "=l"(d) : "f"(lo), "f"(hi))
#define UNPACK2(lo, hi, d) \
    asm("mov.b64 {%0, %1}, %2;" : "=f"(lo), "=f"(hi) : "l"(d))

// Scratch (no cudaMalloc allowed)
__device__ float g_qkv[(size_t)BS * SEQ * QKV3];
__device__ float g_attn[(size_t)BS * SEQ * NX];

// ---------------------------------------------------------------------------
// C[M,N] = A[M,K] @ B[K,N] + bias[N]
// BM=BN=128, BK=16, 256 threads, 8x8 microtile, f32x2 FMAs.
// A stored in smem as duplicated pairs so the broadcast operand needs no packs.
// ---------------------------------------------------------------------------
__global__ __launch_bounds__(256) void gemm_bias_kernel(
    const float* __restrict__ A, const float* __restrict__ B,
    const float* __restrict__ bias, float* __restrict__ C,
    int M, int N, int K)
{
    constexpr int BM = 128, BN = 128, BK = 16;
    __shared__ ull   As2[BK][BM];   // As2[k][m] = (a,a) duplicated   (16 KB)
    __shared__ float Bs[BK][BN];    // (8 KB)

    const int tid = threadIdx.x;
    const int tx = tid & 15;        // 8 cols each
    const int ty = tid >> 4;        // 8 rows each
    const int row0 = blockIdx.y * BM;
    const int col0 = blockIdx.x * BN;

    ull acc2[8][4];                 // (0.f,0.f) == 0ull
    #pragma unroll
    for (int i = 0; i < 8; i++)
        #pragma unroll
        for (int j = 0; j < 4; j++) acc2[i][j] = 0ull;

    for (int k0 = 0; k0 < K; k0 += BK) {
        // A tile: 128x16 floats = 512 float4, 2 per thread, store duplicated
        #pragma unroll
        for (int i = tid; i < BM * BK / 4; i += 256) {
            int r  = i >> 2;
            int c4 = i & 3;
            float4 t = *(const float4*)&A[(size_t)(row0 + r) * K + k0 + c4 * 4];
            ull d0, d1, d2, d3;
            PACK2(d0, t.x, t.x); PACK2(d1, t.y, t.y);
            PACK2(d2, t.z, t.z); PACK2(d3, t.w, t.w);
            As2[c4 * 4 + 0][r] = d0;
            As2[c4 * 4 + 1][r] = d1;
            As2[c4 * 4 + 2][r] = d2;
            As2[c4 * 4 + 3][r] = d3;
        }
        // B tile: 16x128 floats = 512 float4, 2 per thread
        #pragma unroll
        for (int i = tid; i < BK * BN / 4; i += 256) {
            int r = i >> 5;
            int c = i & 31;
            *(float4*)&Bs[r][c * 4] =
                *(const float4*)&B[(size_t)(k0 + r) * N + col0 + c * 4];
        }
        __syncthreads();

        #pragma unroll
        for (int kk = 0; kk < BK; kk++) {
            // 8 duplicated a's: 4 x LDS.128 (intra-warp broadcast, conflict-free)
            ulonglong2 a01 = *(const ulonglong2*)&As2[kk][ty * 8 + 0];
            ulonglong2 a23 = *(const ulonglong2*)&As2[kk][ty * 8 + 2];
            ulonglong2 a45 = *(const ulonglong2*)&As2[kk][ty * 8 + 4];
            ulonglong2 a67 = *(const ulonglong2*)&As2[kk][ty * 8 + 6];
            // 8 b's as 4 naturally-packed pairs: 2 x LDS.128
            ulonglong2 b01 = *(const ulonglong2*)&Bs[kk][tx * 8];
            ulonglong2 b23 = *(const ulonglong2*)&Bs[kk][tx * 8 + 4];
            ull aa[8] = {a01.x, a01.y, a23.x, a23.y, a45.x, a45.y, a67.x, a67.y};
            ull bp[4] = {b01.x, b01.y, b23.x, b23.y};
            #pragma unroll
            for (int i = 0; i < 8; i++)
                #pragma unroll
                for (int jp = 0; jp < 4; jp++)
                    FMA2(acc2[i][jp], aa[i], bp[jp], acc2[i][jp]);
        }
        __syncthreads();
    }

    float4 bi0 = *(const float4*)&bias[col0 + tx * 8];
    float4 bi1 = *(const float4*)&bias[col0 + tx * 8 + 4];
    #pragma unroll
    for (int i = 0; i < 8; i++) {
        int r = row0 + ty * 8 + i;
        float c0, c1, c2, c3, c4, c5, c6, c7;
        UNPACK2(c0, c1, acc2[i][0]);
        UNPACK2(c2, c3, acc2[i][1]);
        UNPACK2(c4, c5, acc2[i][2]);
        UNPACK2(c6, c7, acc2[i][3]);
        float4 o0 = {c0 + bi0.x, c1 + bi0.y, c2 + bi0.z, c3 + bi0.w};
        float4 o1 = {c4 + bi1.x, c5 + bi1.y, c6 + bi1.z, c7 + bi1.w};
        *(float4*)&C[(size_t)r * N + col0 + tx * 8]     = o0;
        *(float4*)&C[(size_t)r * N + col0 + tx * 8 + 4] = o1;
    }
}

// ---------------------------------------------------------------------------
// Flash attention over the "raw reshape" layout, f32x2 inner loops.
// q[b,h,s,d] = qkv[b][u/12][(u%12)*64 + d],   u = h*2048 + s
// k: +768 channel offset; v: +1536. out[b,s,h*64+d].
// ---------------------------------------------------------------------------
__global__ __launch_bounds__(128) void attn_kernel(
    const float* __restrict__ qkv, const float* __restrict__ amask,
    float* __restrict__ attn_out)
{
    constexpr int BM = 128, BN = 32;
    const int qb  = blockIdx.x;
    const int h   = blockIdx.y;
    const int b   = blockIdx.z;
    const int tid = threadIdx.x;
    const int qidx = qb * BM + tid;

    __shared__ float Ks[BN][HD];
    __shared__ float Vs[BN][HD];
    __shared__ float Ams[SEQ];

    const float* base = qkv + (size_t)b * SEQ * QKV3;

    for (int i = tid; i < SEQ; i += BM) Ams[i] = amask[b * SEQ + i];

    // q as 32 packed pairs (rows are contiguous & 256B-aligned in gmem)
    ull q2[HD / 2];
    {
        int u = h * SEQ + qidx;
        const ulonglong2* qp =
            (const ulonglong2*)(base + (u / 12) * QKV3 + (u % 12) * HD);
        #pragma unroll
        for (int i = 0; i < HD / 4; i++) {
            ulonglong2 t = qp[i];
            q2[2 * i]     = t.x;
            q2[2 * i + 1] = t.y;
        }
    }

    ull acc2[HD / 2];
    #pragma unroll
    for (int d = 0; d < HD / 2; d++) acc2[d] = 0ull;
    float m = -3.0e38f, l = 0.f;

    const int nkb = (qb * BM + BM) / BN;   // causal
    for (int kb = 0; kb < nkb; kb++) {
        const int k0 = kb * BN;
        __syncthreads();   // protect previous iteration's Ks/Vs reads
        #pragma unroll
        for (int i = tid; i < BN * HD / 4; i += BM) {
            int j  = i >> 4;
            int d4 = i & 15;
            int u = h * SEQ + k0 + j;
            const float* rowbase = base + (u / 12) * QKV3 + (u % 12) * HD + d4 * 4;
            ((float4*)Ks)[i] = *(const float4*)(rowbase + NX);       // K
            ((float4*)Vs)[i] = *(const float4*)(rowbase + 2 * NX);   // V
        }
        __syncthreads();

        float s[BN];
        #pragma unroll
        for (int j = 0; j < BN; j++) {
            const ulonglong2* kp = (const ulonglong2*)Ks[j];
            ull c0 = 0ull, c1 = 0ull, c2 = 0ull, c3 = 0ull;
            #pragma unroll
            for (int i = 0; i < 8; i++) {
                ulonglong2 kv0 = kp[2 * i];
                ulonglong2 kv1 = kp[2 * i + 1];
                FMA2(c0, q2[4 * i + 0], kv0.x, c0);
                FMA2(c1, q2[4 * i + 1], kv0.y, c1);
                FMA2(c2, q2[4 * i + 2], kv1.x, c2);
                FMA2(c3, q2[4 * i + 3], kv1.y, c3);
            }
            float f0, f1, f2, f3, f4, f5, f6, f7;
            UNPACK2(f0, f1, c0); UNPACK2(f2, f3, c1);
            UNPACK2(f4, f5, c2); UNPACK2(f6, f7, c3);
            float sum = ((f0 + f1) + (f2 + f3)) + ((f4 + f5) + (f6 + f7));
            int k = k0 + j;
            s[j] = (k <= qidx) ? (sum * 0.125f + Ams[k]) : (-10000.f + Ams[k]);
        }

        float mb = s[0];
        #pragma unroll
        for (int j = 1; j < BN; j++) mb = fmaxf(mb, s[j]);
        float mn = fmaxf(m, mb);
        float corr = __expf(m - mn);
        l *= corr;
        ull corr2;
        PACK2(corr2, corr, corr);
        #pragma unroll
        for (int d = 0; d < HD / 2; d++) MUL2(acc2[d], acc2[d], corr2);

        #pragma unroll
        for (int j = 0; j < BN; j++) {
            float p = __expf(s[j] - mn);
            l += p;
            ull pp;
            PACK2(pp, p, p);
            const ulonglong2* vp = (const ulonglong2*)Vs[j];
            #pragma unroll
            for (int i = 0; i < HD / 4; i++) {
                ulonglong2 vv = vp[i];
                FMA2(acc2[2 * i],     pp, vv.x, acc2[2 * i]);
                FMA2(acc2[2 * i + 1], pp, vv.y, acc2[2 * i + 1]);
            }
        }
        m = mn;
    }

    float inv = 1.f / l;
    ull inv2;
    PACK2(inv2, inv, inv);
    ulonglong2* op =
        (ulonglong2*)(attn_out + ((size_t)b * SEQ + qidx) * NX + h * HD);
    #pragma unroll
    for (int i = 0; i < HD / 4; i++) {
        ulonglong2 t;
        MUL2(t.x, acc2[2 * i],     inv2);
        MUL2(t.y, acc2[2 * i + 1], inv2);
        op[i] = t;
    }
}

// ---------------------------------------------------------------------------
extern "C" void kernel_launch(void* const* d_in, const int* in_sizes, int n_in,
                              void* d_out, int out_size)
{
    const float* hidden = (const float*)d_in[0];
    const float* amask  = (const float*)d_in[1];
    const float* w_attn = (const float*)d_in[2];
    const float* b_attn = (const float*)d_in[3];
    const float* w_proj = (const float*)d_in[4];
    const float* b_proj = (const float*)d_in[5];
    float* out = (float*)d_out;

    float *qkv, *attn;
    cudaGetSymbolAddress((void**)&qkv,  g_qkv);
    cudaGetSymbolAddress((void**)&attn, g_attn);

    const int M = BS * SEQ;   // 4096

    gemm_bias_kernel<<<dim3(QKV3 / 128, M / 128), 256>>>(hidden, w_attn, b_attn, qkv, M, QKV3, NX);

    attn_kernel<<<dim3(SEQ / 128, NHEAD, BS), 128>>>(qkv, amask, attn);

    gemm_bias_kernel<<<dim3(NX / 128, M / 128), 256>>>(attn, w_proj, b_proj, out, M, NX, NX);
}